// round 1
// baseline (speedup 1.0000x reference)
#include <cuda_runtime.h>
#include <cuda_bf16.h>
#include <cstddef>

// y[token, k*128 + d] = (1/sqrt(32)) * sum_j H32[k,j] * x[token, j*128 + d]
// H32 = Sylvester Hadamard -> fast Walsh-Hadamard butterfly (5 stages).
//
// One block per token (row of 4096 f32). 128 threads; thread d owns lane d
// of all 32 heads. Loads/stores are warp-coalesced 128B requests.

#define HEADS 32
#define HEAD_DIM 128
#define HIDDEN 4096

__global__ __launch_bounds__(HEAD_DIM, 8)
void fwht_cross_head_kernel(const float* __restrict__ x,
                            float* __restrict__ y,
                            int num_tokens)
{
    const int token = blockIdx.x;
    if (token >= num_tokens) return;
    const int d = threadIdx.x;  // 0..127

    const float* __restrict__ xr = x + (size_t)token * HIDDEN + d;
    float* __restrict__ yr       = y + (size_t)token * HIDDEN + d;

    float v[HEADS];
    #pragma unroll
    for (int k = 0; k < HEADS; ++k) {
        v[k] = __ldg(xr + k * HEAD_DIM);
    }

    // 5-stage fast Walsh-Hadamard transform across the head index.
    #pragma unroll
    for (int s = 1; s < HEADS; s <<= 1) {
        #pragma unroll
        for (int i = 0; i < HEADS; ++i) {
            if ((i & s) == 0) {
                const float a = v[i];
                const float b = v[i + s];
                v[i]     = a + b;
                v[i + s] = a - b;
            }
        }
    }

    const float scale = 0.17677669529663687f;  // 1/sqrt(32)
    #pragma unroll
    for (int k = 0; k < HEADS; ++k) {
        yr[k * HEAD_DIM] = v[k] * scale;
    }
}

extern "C" void kernel_launch(void* const* d_in, const int* in_sizes, int n_in,
                              void* d_out, int out_size)
{
    const float* x = (const float*)d_in[0];
    // d_in[1] (had_K) is the deterministic 32x32 Sylvester Hadamard; the
    // butterfly above implements it exactly, so it is not read on device.
    float* y = (float*)d_out;

    const int num_tokens = in_sizes[0] / HIDDEN;  // 4*4096 = 16384

    dim3 grid(num_tokens);
    dim3 block(HEAD_DIM);
    fwht_cross_head_kernel<<<grid, block>>>(x, y, num_tokens);
}